// round 9
// baseline (speedup 1.0000x reference)
#include <cuda_runtime.h>
#include <cuda_fp16.h>
#include <cstdint>

#define NB_CAT   8192
#define RANK     16
#define N_COLS   4
#define N_GRP    8            // (col, rank-half)
#define CHUNK    2048         // pairs per work-steal grab
#define MAX_PAIRS 1048576

// R9: route the 8M random row-gathers through the SMEM crossbar (128B/cyc/SM)
// instead of L1tex (~1 row/cyc). Table split into 8 slices of 128KB
// (grp = col*2 + rankhalf); each SM owns one slice via %smid&7; CTAs
// work-steal pair-chunks within their group; partials go to a static
// scratch; a combine kernel sums the 8 partials per pair (deterministic).

__device__ __half2  g_cfr[N_GRP * NB_CAT * 4];        // 4 MB: [grp][cat][4 x half2]
__device__ float    g_part[(size_t)N_GRP * MAX_PAIRS]; // 32 MB scratch
__device__ unsigned g_next[N_GRP];                     // per-group chunk counters

// --- Kernel 1: convert fp32 cf [c][cat][r] -> fp16 [grp][cat][16B]; zero counters.
__global__ __launch_bounds__(256) void convert_kernel(const float* __restrict__ cf)
{
    const int i = blockIdx.x * blockDim.x + threadIdx.x;   // float2 (=2 ranks) index
    const int n = N_COLS * NB_CAT * RANK / 2;              // 1,048,576
    if (i < n) {
        const float2 v = __ldcg((const float2*)cf + i);
        const int c   = i >> 16;          // / (NB_CAT * 8)
        const int rem = i & 65535;
        const int cat = rem >> 3;
        const int j   = rem & 7;          // half2 index within row (r = 2j)
        const int grp = c * 2 + (j >> 2); // rank-half = (r >= 8)
        const int dj  = j & 3;
        g_cfr[((grp * NB_CAT + cat) << 2) + dj] = __float22half2_rn(v);
    }
    if (blockIdx.x == 0 && threadIdx.x < N_GRP) g_next[threadIdx.x] = 0u;
}

// --- Kernel 2: per-SM slice-resident gather. 148 CTAs x 1024 thr, 128KB smem.
__global__ __launch_bounds__(1024, 1) void gather_kernel(
    const int*   __restrict__ x,
    const int*   __restrict__ y,
    const float* __restrict__ stdv,   // [N_COLS, NB_CAT]
    int n_pairs)
{
    extern __shared__ __align__(16) char sm[];   // 8192 cats x 16B = 128KB
    __shared__ unsigned s_chunk;

    unsigned smid; asm("mov.u32 %0, %%smid;" : "=r"(smid));
    const int grp  = (int)(smid & 7u);
    const int col  = grp >> 1;
    const int half = grp & 1;

    // Stage this group's slice (dense 128KB copy from the pre-transposed table)
    {
        const uint4* src = (const uint4*)g_cfr + (size_t)grp * NB_CAT;
        uint4* dst = (uint4*)sm;
        for (int cat = threadIdx.x; cat < NB_CAT; cat += 1024)
            dst[cat] = src[cat];
    }
    __syncthreads();

    const int warp = threadIdx.x >> 5;
    const int lane = threadIdx.x & 31;
    const int nchunks = (n_pairs + CHUNK - 1) / CHUNK;
    const float* std_c = stdv + col * NB_CAT;
    float* part_g = g_part + (size_t)grp * MAX_PAIRS;

    for (;;) {
        if (threadIdx.x == 0) s_chunk = atomicAdd(&g_next[grp], 1u);
        __syncthreads();
        const unsigned ch = s_chunk;
        __syncthreads();                      // protect s_chunk before next write
        if (ch >= (unsigned)nchunks) break;

        const int cbase = (int)ch * CHUNK + warp * 64;   // 32 warps x 64 pairs = CHUNK

        #pragma unroll
        for (int it = 0; it < 2; it++) {
            const int p = cbase + it * 32 + lane;
            if (p >= n_pairs) continue;

            const int xi = __ldcg(x + (size_t)p * N_COLS + col);
            const int yi = __ldcg(y + (size_t)p * N_COLS + col);

            // One 16B half-row per side from smem (LDS.128)
            const uint4 a = *(const uint4*)(sm + ((size_t)xi << 4));
            const uint4 b = *(const uint4*)(sm + ((size_t)yi << 4));

            __half2 p01 = __hmul2(*(const __half2*)&a.x, *(const __half2*)&b.x);
            p01 = __hfma2(*(const __half2*)&a.y, *(const __half2*)&b.y, p01);
            __half2 p23 = __hmul2(*(const __half2*)&a.z, *(const __half2*)&b.z);
            p23 = __hfma2(*(const __half2*)&a.w, *(const __half2*)&b.w, p23);

            const float2 f0 = __half22float2(p01);
            const float2 f1 = __half22float2(p23);
            float acc = (f0.x + f0.y) + (f1.x + f1.y);

            // Diagonal term added exactly once per (pair,col): by the half==0 group
            if (half == 0 && xi == yi) {
                const float s = std_c[xi];
                acc += s * s;
            }

            part_g[p] = acc;   // coalesced 128B per warp
        }
    }
}

// --- Kernel 3: out[p] = sum over 8 group partials (fixed order -> deterministic)
__global__ __launch_bounds__(256) void combine_kernel(float* __restrict__ out, int n_pairs)
{
    const int i = blockIdx.x * blockDim.x + threadIdx.x;   // float4 index
    const int n4 = n_pairs >> 2;
    if (i < n4) {
        float4 s = make_float4(0.f, 0.f, 0.f, 0.f);
        #pragma unroll
        for (int g = 0; g < N_GRP; g++) {
            const float4 v = __ldcg((const float4*)(g_part + (size_t)g * MAX_PAIRS) + i);
            s.x += v.x; s.y += v.y; s.z += v.z; s.w += v.w;
        }
        ((float4*)out)[i] = s;
    }
}

extern "C" void kernel_launch(void* const* d_in, const int* in_sizes, int n_in,
                              void* d_out, int out_size)
{
    const int*   x    = (const int*)d_in[0];
    const int*   y    = (const int*)d_in[1];
    const float* cf   = (const float*)d_in[2];
    const float* stdv = (const float*)d_in[3];
    float*       out  = (float*)d_out;

    const int n_pairs = out_size;  // 1048576

    static bool attr_set = false;
    if (!attr_set) {
        cudaFuncSetAttribute(gather_kernel,
                             cudaFuncAttributeMaxDynamicSharedMemorySize,
                             NB_CAT * 16);
        attr_set = true;
    }

    // 1) transpose+convert table, zero work counters
    {
        const int n = N_COLS * NB_CAT * RANK / 2;
        convert_kernel<<<(n + 255) / 256, 256>>>(cf);
    }
    // 2) slice-resident gather (one CTA per SM; 128KB dynamic smem)
    gather_kernel<<<148, 1024, NB_CAT * 16>>>(x, y, stdv, n_pairs);
    // 3) combine partials
    {
        const int n4 = n_pairs >> 2;
        combine_kernel<<<(n4 + 255) / 256, 256>>>(out, n_pairs);
    }
}

// round 10
// speedup vs baseline: 1.6102x; 1.6102x over previous
#include <cuda_runtime.h>
#include <cuda_fp16.h>
#include <cstdint>

#define NB_CAT  8192
#define RANK    16
#define N_COLS  4

// R10: R6's proven MLP structure (explicit 8-load batch + index prefetch,
// occ 6 = 42-reg budget so the batch stays in flight) + half2 math
// (HMUL2+HFMA2 per column: ~5 issue slots/col vs ~12 for the fp32 convert
// storm). R8 proved half2 correct but strangled it with a 32-reg cap; this
// is the first test of half2 WITH register room.

__device__ __half2 g_cfh[N_COLS * NB_CAT * RANK / 2];   // 4 MB, layout = cf

// Vectorized convert: each thread reads 2x float4 (32B) -> writes uint4 (16B).
__global__ __launch_bounds__(256) void convert_cf_kernel(const float* __restrict__ cf)
{
    const int i = blockIdx.x * blockDim.x + threadIdx.x;   // uint4 (=8 halves) index
    const int n = N_COLS * NB_CAT * RANK / 8;              // 262,144
    if (i < n) {
        const float4 v0 = __ldcg((const float4*)cf + i * 2);
        const float4 v1 = __ldcg((const float4*)cf + i * 2 + 1);
        uint4 o;
        *(__half2*)&o.x = __float22half2_rn(make_float2(v0.x, v0.y));
        *(__half2*)&o.y = __float22half2_rn(make_float2(v0.z, v0.w));
        *(__half2*)&o.z = __float22half2_rn(make_float2(v1.x, v1.y));
        *(__half2*)&o.w = __float22half2_rn(make_float2(v1.z, v1.w));
        ((uint4*)g_cfh)[i] = o;
    }
}

__global__ __launch_bounds__(256, 6) void pair_cov_kernel(
    const int*   __restrict__ x,
    const int*   __restrict__ y,
    const float* __restrict__ stdv,   // [N_COLS, NB_CAT]
    float*       __restrict__ out,
    int n_pairs)
{
    const int lane = threadIdx.x & 31;
    const int sub  = lane & 3;        // 8B chunk of the 32B fp16 row
    const int unit = lane >> 2;       // pair slot (0..7) within warp-iter

    const int warp_global = (int)((blockIdx.x * blockDim.x + threadIdx.x) >> 5);
    const int nwarps      = (int)((gridDim.x * blockDim.x) >> 5);

    const uint2* cfh = (const uint2*)g_cfh;   // row r -> cfh[r*4 + sub]

    int base = warp_global * 8;
    if (base >= n_pairs) return;

    // Prime the index pipeline
    int4 xi = __ldcg((const int4*)x + base + unit);
    int4 yi = __ldcg((const int4*)y + base + unit);

    while (base < n_pairs) {
        const int nbase = base + nwarps * 8;

        // ---- Issue all 8 row gathers back-to-back (MLP = 8) ----
        uint2 av0 = cfh[(size_t)(0 * NB_CAT + xi.x) * 4 + sub];
        uint2 bv0 = cfh[(size_t)(0 * NB_CAT + yi.x) * 4 + sub];
        uint2 av1 = cfh[(size_t)(1 * NB_CAT + xi.y) * 4 + sub];
        uint2 bv1 = cfh[(size_t)(1 * NB_CAT + yi.y) * 4 + sub];
        uint2 av2 = cfh[(size_t)(2 * NB_CAT + xi.z) * 4 + sub];
        uint2 bv2 = cfh[(size_t)(2 * NB_CAT + yi.z) * 4 + sub];
        uint2 av3 = cfh[(size_t)(3 * NB_CAT + xi.w) * 4 + sub];
        uint2 bv3 = cfh[(size_t)(3 * NB_CAT + yi.w) * 4 + sub];

        // ---- Diagonal term while gathers fly (fp32 std, exact) ----
        float acc = 0.0f;
        {
            const int xd = (sub == 0) ? xi.x : (sub == 1) ? xi.y : (sub == 2) ? xi.z : xi.w;
            const int yd = (sub == 0) ? yi.x : (sub == 1) ? yi.y : (sub == 2) ? yi.z : yi.w;
            if (xd == yd) {
                const float s = stdv[sub * NB_CAT + xd];
                acc = s * s;
            }
        }

        // ---- Prefetch next iteration's indices (hide DRAM latency) ----
        int4 nxi, nyi;
        if (nbase < n_pairs) {
            nxi = __ldcg((const int4*)x + nbase + unit);
            nyi = __ldcg((const int4*)y + nbase + unit);
        }
        xi = nxi;
        yi = nyi;

        // ---- Math: per-column dot in half2, fp32 cross-column accumulate ----
        __half2 p0 = __hmul2(*(const __half2*)&av0.x, *(const __half2*)&bv0.x);
        p0 = __hfma2(*(const __half2*)&av0.y, *(const __half2*)&bv0.y, p0);
        __half2 p1 = __hmul2(*(const __half2*)&av1.x, *(const __half2*)&bv1.x);
        p1 = __hfma2(*(const __half2*)&av1.y, *(const __half2*)&bv1.y, p1);
        __half2 p2 = __hmul2(*(const __half2*)&av2.x, *(const __half2*)&bv2.x);
        p2 = __hfma2(*(const __half2*)&av2.y, *(const __half2*)&bv2.y, p2);
        __half2 p3 = __hmul2(*(const __half2*)&av3.x, *(const __half2*)&bv3.x);
        p3 = __hfma2(*(const __half2*)&av3.y, *(const __half2*)&bv3.y, p3);

        const float2 f0 = __half22float2(p0);
        const float2 f1 = __half22float2(p1);
        const float2 f2 = __half22float2(p2);
        const float2 f3 = __half22float2(p3);
        acc += (f0.x + f0.y) + (f1.x + f1.y);
        acc += (f2.x + f2.y) + (f3.x + f3.y);

        // ---- Reduce over the 4 chunk lanes; lane 0 of each unit writes ----
        acc += __shfl_xor_sync(0xffffffffu, acc, 1);
        acc += __shfl_xor_sync(0xffffffffu, acc, 2);

        if (sub == 0) {
            out[base + unit] = acc;   // 8 lanes -> 32 contiguous bytes -> 1 wf
        }

        base = nbase;
    }
}

extern "C" void kernel_launch(void* const* d_in, const int* in_sizes, int n_in,
                              void* d_out, int out_size)
{
    const int*   x    = (const int*)d_in[0];
    const int*   y    = (const int*)d_in[1];
    const float* cf   = (const float*)d_in[2];
    const float* stdv = (const float*)d_in[3];
    float*       out  = (float*)d_out;

    const int n_pairs = out_size;  // 1048576

    // 1) Convert covar_factor fp32 -> fp16 (vectorized, 2x MLP per thread)
    {
        const int n = N_COLS * NB_CAT * RANK / 8;
        convert_cf_kernel<<<(n + 255) / 256, 256>>>(cf);
    }

    // 2) Main gather kernel: single resident wave at 6 blocks/SM
    {
        const int threads = 256;
        const int blocks  = 148 * 6;
        pair_cov_kernel<<<blocks, threads>>>(x, y, stdv, out, n_pairs);
    }
}

// round 11
// speedup vs baseline: 1.6841x; 1.0459x over previous
#include <cuda_runtime.h>
#include <cuda_fp16.h>
#include <cstdint>

#define NB_CAT  8192
#define RANK    16
#define N_COLS  4

// R11: discriminate latency-limit vs miss-path-limit. Double-batch: 16 row
// gathers in flight per warp (2 pair-groups/iter) at occ 4 (64-reg budget,
// 32 warps/SM) -> 512 in-flight rows/SM vs R10's 336. If the ~0.85 wf/cyc
// plateau is queue-inflated-latency-limited, this lifts it toward 1.0.

__device__ __half2 g_cfh[N_COLS * NB_CAT * RANK / 2];   // 4 MB, layout = cf

__global__ __launch_bounds__(256) void convert_cf_kernel(const float* __restrict__ cf)
{
    const int i = blockIdx.x * blockDim.x + threadIdx.x;   // uint4 (=8 halves) index
    const int n = N_COLS * NB_CAT * RANK / 8;              // 262,144
    if (i < n) {
        const float4 v0 = __ldcg((const float4*)cf + i * 2);
        const float4 v1 = __ldcg((const float4*)cf + i * 2 + 1);
        uint4 o;
        *(__half2*)&o.x = __float22half2_rn(make_float2(v0.x, v0.y));
        *(__half2*)&o.y = __float22half2_rn(make_float2(v0.z, v0.w));
        *(__half2*)&o.z = __float22half2_rn(make_float2(v1.x, v1.y));
        *(__half2*)&o.w = __float22half2_rn(make_float2(v1.z, v1.w));
        ((uint4*)g_cfh)[i] = o;
    }
}

__device__ __forceinline__ float dot_row_group(
    const uint2& a0, const uint2& b0, const uint2& a1, const uint2& b1,
    const uint2& a2, const uint2& b2, const uint2& a3, const uint2& b3)
{
    __half2 p0 = __hmul2(*(const __half2*)&a0.x, *(const __half2*)&b0.x);
    p0 = __hfma2(*(const __half2*)&a0.y, *(const __half2*)&b0.y, p0);
    __half2 p1 = __hmul2(*(const __half2*)&a1.x, *(const __half2*)&b1.x);
    p1 = __hfma2(*(const __half2*)&a1.y, *(const __half2*)&b1.y, p1);
    __half2 p2 = __hmul2(*(const __half2*)&a2.x, *(const __half2*)&b2.x);
    p2 = __hfma2(*(const __half2*)&a2.y, *(const __half2*)&b2.y, p2);
    __half2 p3 = __hmul2(*(const __half2*)&a3.x, *(const __half2*)&b3.x);
    p3 = __hfma2(*(const __half2*)&a3.y, *(const __half2*)&b3.y, p3);
    const float2 f0 = __half22float2(p0);
    const float2 f1 = __half22float2(p1);
    const float2 f2 = __half22float2(p2);
    const float2 f3 = __half22float2(p3);
    return (f0.x + f0.y) + (f1.x + f1.y) + (f2.x + f2.y) + (f3.x + f3.y);
}

__device__ __forceinline__ float diag_term(
    const int4& xi, const int4& yi, int sub, const float* __restrict__ stdv)
{
    const int xd = (sub == 0) ? xi.x : (sub == 1) ? xi.y : (sub == 2) ? xi.z : xi.w;
    const int yd = (sub == 0) ? yi.x : (sub == 1) ? yi.y : (sub == 2) ? yi.z : yi.w;
    if (xd == yd) {
        const float s = stdv[sub * NB_CAT + xd];
        return s * s;
    }
    return 0.0f;
}

__global__ __launch_bounds__(256, 4) void pair_cov_kernel(
    const int*   __restrict__ x,
    const int*   __restrict__ y,
    const float* __restrict__ stdv,   // [N_COLS, NB_CAT]
    float*       __restrict__ out,
    int n_pairs)
{
    const int lane = threadIdx.x & 31;
    const int sub  = lane & 3;        // 8B chunk of the 32B fp16 row
    const int unit = lane >> 2;       // pair slot (0..7) within group

    const int warp_global = (int)((blockIdx.x * blockDim.x + threadIdx.x) >> 5);
    const int nwarps      = (int)((gridDim.x * blockDim.x) >> 5);

    const uint2* cfh = (const uint2*)g_cfh;   // row r -> cfh[r*4 + sub]

    int base = warp_global * 16;
    if (base >= n_pairs) return;

    // Prime index pipeline for both groups (A: base+unit, B: base+8+unit)
    int4 xiA = __ldcg((const int4*)x + base + unit);
    int4 yiA = __ldcg((const int4*)y + base + unit);
    int4 xiB = __ldcg((const int4*)x + base + 8 + unit);
    int4 yiB = __ldcg((const int4*)y + base + 8 + unit);

    while (base < n_pairs) {
        const int nbase = base + nwarps * 16;

        // ---- Issue all 16 row gathers back-to-back (MLP = 16) ----
        uint2 aA0 = cfh[(size_t)(0 * NB_CAT + xiA.x) * 4 + sub];
        uint2 bA0 = cfh[(size_t)(0 * NB_CAT + yiA.x) * 4 + sub];
        uint2 aA1 = cfh[(size_t)(1 * NB_CAT + xiA.y) * 4 + sub];
        uint2 bA1 = cfh[(size_t)(1 * NB_CAT + yiA.y) * 4 + sub];
        uint2 aA2 = cfh[(size_t)(2 * NB_CAT + xiA.z) * 4 + sub];
        uint2 bA2 = cfh[(size_t)(2 * NB_CAT + yiA.z) * 4 + sub];
        uint2 aA3 = cfh[(size_t)(3 * NB_CAT + xiA.w) * 4 + sub];
        uint2 bA3 = cfh[(size_t)(3 * NB_CAT + yiA.w) * 4 + sub];
        uint2 aB0 = cfh[(size_t)(0 * NB_CAT + xiB.x) * 4 + sub];
        uint2 bB0 = cfh[(size_t)(0 * NB_CAT + yiB.x) * 4 + sub];
        uint2 aB1 = cfh[(size_t)(1 * NB_CAT + xiB.y) * 4 + sub];
        uint2 bB1 = cfh[(size_t)(1 * NB_CAT + yiB.y) * 4 + sub];
        uint2 aB2 = cfh[(size_t)(2 * NB_CAT + xiB.z) * 4 + sub];
        uint2 bB2 = cfh[(size_t)(2 * NB_CAT + yiB.z) * 4 + sub];
        uint2 aB3 = cfh[(size_t)(3 * NB_CAT + xiB.w) * 4 + sub];
        uint2 bB3 = cfh[(size_t)(3 * NB_CAT + yiB.w) * 4 + sub];

        // ---- Diagonal terms while gathers fly (indices die after this) ----
        float accA = diag_term(xiA, yiA, sub, stdv);
        float accB = diag_term(xiB, yiB, sub, stdv);

        // ---- Prefetch next iteration's indices ----
        if (nbase < n_pairs) {
            xiA = __ldcg((const int4*)x + nbase + unit);
            yiA = __ldcg((const int4*)y + nbase + unit);
            xiB = __ldcg((const int4*)x + nbase + 8 + unit);
            yiB = __ldcg((const int4*)y + nbase + 8 + unit);
        }

        // ---- Math: half2 dots, fp32 accumulate ----
        accA += dot_row_group(aA0, bA0, aA1, bA1, aA2, bA2, aA3, bA3);
        accB += dot_row_group(aB0, bB0, aB1, bB1, aB2, bB2, aB3, bB3);

        // ---- Reduce over the 4 chunk lanes; lane 0 of each unit writes ----
        accA += __shfl_xor_sync(0xffffffffu, accA, 1);
        accA += __shfl_xor_sync(0xffffffffu, accA, 2);
        accB += __shfl_xor_sync(0xffffffffu, accB, 1);
        accB += __shfl_xor_sync(0xffffffffu, accB, 2);

        if (sub == 0) {
            out[base + unit]     = accA;   // 8 lanes -> 32B -> 1 wf
            out[base + 8 + unit] = accB;   // 8 lanes -> 32B -> 1 wf
        }

        base = nbase;
    }
}

extern "C" void kernel_launch(void* const* d_in, const int* in_sizes, int n_in,
                              void* d_out, int out_size)
{
    const int*   x    = (const int*)d_in[0];
    const int*   y    = (const int*)d_in[1];
    const float* cf   = (const float*)d_in[2];
    const float* stdv = (const float*)d_in[3];
    float*       out  = (float*)d_out;

    const int n_pairs = out_size;  // 1048576

    // 1) Convert covar_factor fp32 -> fp16 (vectorized)
    {
        const int n = N_COLS * NB_CAT * RANK / 8;
        convert_cf_kernel<<<(n + 255) / 256, 256>>>(cf);
    }

    // 2) Main gather kernel: single resident wave at 4 blocks/SM
    {
        const int threads = 256;
        const int blocks  = 148 * 4;
        pair_cov_kernel<<<blocks, threads>>>(x, y, stdv, out, n_pairs);
    }
}